// round 11
// baseline (speedup 1.0000x reference)
#include <cuda_runtime.h>
#include <cuda_fp16.h>
#include <math.h>
#include <stdint.h>

#define NN 50000
#define NE 500000
#define DD 128
#define NCHUNK 26
#define NBLK 196   // ceil(50000/256)

// ---------------- device scratch ----------------
__device__ int    g_deg[NN];
__device__ int    g_pos[NN];
__device__ int    g_ptr[NN];        // scanA: block-local inclusive
__device__ int    g_ptr2[NN + 1];   // global exclusive (final CSR)
__device__ int    g_bsum[NBLK];
__device__ float  g_partial[NBLK];
__device__ int    g_ssrc[NE];
__device__ int    g_srel[NE];
__device__ float  g_sw[NE];
__device__ float  g_scale[NN];
__device__ __half g_feats[(size_t)NN * 512];
__device__ float  g_xa[(size_t)NN * DD];
__device__ float  g_xb[(size_t)NN * DD];
// transposed fp16 weight tiles: [4 layers][26 chunks][128 n][64 k]
__device__ __half g_Bhi[4 * NCHUNK * 8192];

__device__ __forceinline__ uint32_t smem_u32(const void* p) {
    uint32_t a;
    asm("{ .reg .u64 t; cvta.to.shared.u64 t, %1; cvt.u32.u64 %0, t; }" : "=r"(a) : "l"(p));
    return a;
}
__device__ __forceinline__ void ldm_x4(uint32_t addr, uint32_t* r) {
    asm volatile("ldmatrix.sync.aligned.m8n8.x4.shared.b16 {%0,%1,%2,%3}, [%4];"
                 : "=r"(r[0]), "=r"(r[1]), "=r"(r[2]), "=r"(r[3]) : "r"(addr));
}
__device__ __forceinline__ void mma16816(float* c, const uint32_t* a, uint32_t b0, uint32_t b1) {
    asm volatile(
        "mma.sync.aligned.m16n8k16.row.col.f32.f16.f16.f32 "
        "{%0,%1,%2,%3}, {%4,%5,%6,%7}, {%8,%9}, {%0,%1,%2,%3};"
        : "+f"(c[0]), "+f"(c[1]), "+f"(c[2]), "+f"(c[3])
        : "r"(a[0]), "r"(a[1]), "r"(a[2]), "r"(a[3]), "r"(b0), "r"(b1));
}
__device__ __forceinline__ void cp16(uint32_t dst, const void* src) {
    asm volatile("cp.async.cg.shared.global [%0], [%1], 16;" :: "r"(dst), "l"(src));
}
#define CP_COMMIT() asm volatile("cp.async.commit_group;" ::: "memory")
#define CP_WAIT0()  asm volatile("cp.async.wait_group 0;" ::: "memory")

__device__ __forceinline__ uint2 pack4h(float4 f) {
    __half2 a = __floats2half2_rn(f.x, f.y);
    __half2 b = __floats2half2_rn(f.z, f.w);
    uint2 u;
    u.x = *(uint32_t*)&a;
    u.y = *(uint32_t*)&b;
    return u;
}

// ---------------- CSR build ----------------
__global__ void k_hist(const int* __restrict__ ed) {
    int e = blockIdx.x * blockDim.x + threadIdx.x;
    if (e < NE) atomicAdd(&g_deg[ed[e]], 1);
}
// per-block inclusive scan + per-block log-degree partial sums
__global__ void k_scanA() {
    int b = blockIdx.x, t = threadIdx.x, i = b * 256 + t;
    int v = (i < NN) ? g_deg[i] : 0;
    int lane = t & 31, w = t >> 5;
    int x = v;
#pragma unroll
    for (int off = 1; off < 32; off <<= 1) {
        int y = __shfl_up_sync(0xffffffffu, x, off);
        if (lane >= off) x += y;
    }
    __shared__ int ws[8];
    __shared__ float ls[8];
    if (lane == 31) ws[w] = x;
    // log partial
    float lg = (i < NN) ? logf((float)v + 1.0f) : 0.0f;
#pragma unroll
    for (int off = 16; off > 0; off >>= 1) lg += __shfl_xor_sync(0xffffffffu, lg, off);
    if (lane == 0) ls[w] = lg;
    __syncthreads();
    int add = 0;
#pragma unroll
    for (int j = 0; j < 8; j++) if (j < w) add += ws[j];
    x += add;
    if (i < NN) g_ptr[i] = x;
    if (t == 255) g_bsum[b] = x;
    if (t == 0) {
        float s = 0;
#pragma unroll
        for (int j = 0; j < 8; j++) s += ls[j];
        g_partial[b] = s;
    }
}
// fused: scan block sums + finalize ptr + scatter edges + scale write
__global__ void k_fillB(const int* __restrict__ es, const int* __restrict__ ed,
                        const int* __restrict__ et, const float* __restrict__ ew) {
    __shared__ int sc[256];
    __shared__ int sOff[NBLK + 1];
    __shared__ float fs[256];
    int t = threadIdx.x, b = blockIdx.x;
    int v = (t < NBLK) ? g_bsum[t] : 0;
    sc[t] = v;
    fs[t] = (t < NBLK) ? g_partial[t] : 0.0f;
    __syncthreads();
#pragma unroll
    for (int off = 1; off < 256; off <<= 1) {
        int u = (t >= off) ? sc[t - off] : 0;
        __syncthreads();
        sc[t] += u;
        __syncthreads();
    }
    if (t < NBLK) sOff[t] = sc[t] - v;
    if (t == NBLK - 1) sOff[NBLK] = sc[t];
    __syncthreads();
#pragma unroll
    for (int off = 128; off > 0; off >>= 1) {
        if (t < off) fs[t] += fs[t + off];
        __syncthreads();
    }
    float factor = (float)NN / fs[0];
    int i = b * 256 + t;
    if (i < NN) {
        g_ptr2[i] = g_ptr[i] - g_deg[i] + sOff[i >> 8];
        g_scale[i] = logf((float)g_deg[i] + 1.0f) * factor;
    }
    if (i == 0) g_ptr2[NN] = sOff[NBLK];
    int e = b * 256 + t;
    if (e < NE) {
        int d = ed[e];
        int base = g_ptr[d] - g_deg[d] + sOff[d >> 8];
        int p = atomicAdd(&g_pos[d], 1);
        int slot = base + p;
        g_ssrc[slot] = es[e];
        g_srel[slot] = et[e];
        g_sw[slot] = ew[e];
    }
}

// ---------------- weight prep: smem transpose + fp16 ----------------
__global__ void k_prepw(const float* __restrict__ linw) {
    __shared__ float ts[64][129];
    int tile = blockIdx.x;
    int l = tile / NCHUNK, kt = tile - l * NCHUNK;
    const float* src = linw + ((size_t)l * 1664 + kt * 64) * 128;
    for (int i = threadIdx.x; i < 8192; i += 256) {
        int k = i >> 7, n = i & 127;
        ts[k][n] = src[i];
    }
    __syncthreads();
    __half* bh = g_Bhi + (size_t)tile * 8192;
    for (int i = threadIdx.x; i < 8192; i += 256) {
        int n = i >> 6, kk = i & 63;
        bh[i] = __float2half_rn(ts[kk][n]);
    }
}

// ---------------- aggregation: warp/node, depth-1 prefetch, fp16 feats out ----------------
__global__ void k_aggregate(const float* __restrict__ x, const float* __restrict__ x0,
                            const float* __restrict__ relw) {
    int gw = (blockIdx.x * blockDim.x + threadIdx.x) >> 5;
    int lane = threadIdx.x & 31;
    if (gw >= NN) return;
    int n = gw;
    float4 b = ((const float4*)(x0 + (size_t)n * DD))[lane];
    float4 sum = b, mx = b, mn = b;
    float4 ssq = make_float4(b.x * b.x, b.y * b.y, b.z * b.z, b.w * b.w);
    int p0 = g_ptr2[n], p1 = g_ptr2[n + 1];
    float4 xv, rv;
    float w = 0.f;
    if (p0 < p1) {
        int s = g_ssrc[p0], r = g_srel[p0];
        w = g_sw[p0];
        xv = ((const float4*)(x + (size_t)s * DD))[lane];
        rv = ((const float4*)(relw + (size_t)r * DD))[lane];
    }
    for (int p = p0; p < p1; ++p) {
        float4 cx = xv, cr = rv;
        float cw = w;
        if (p + 1 < p1) {
            int s2 = g_ssrc[p + 1], r2 = g_srel[p + 1];
            w = g_sw[p + 1];
            xv = ((const float4*)(x + (size_t)s2 * DD))[lane];
            rv = ((const float4*)(relw + (size_t)r2 * DD))[lane];
        }
        float4 m = make_float4(cx.x * cr.x * cw, cx.y * cr.y * cw, cx.z * cr.z * cw, cx.w * cr.w * cw);
        sum.x += m.x; sum.y += m.y; sum.z += m.z; sum.w += m.w;
        ssq.x += m.x * m.x; ssq.y += m.y * m.y; ssq.z += m.z * m.z; ssq.w += m.w * m.w;
        mx.x = fmaxf(mx.x, m.x); mx.y = fmaxf(mx.y, m.y); mx.z = fmaxf(mx.z, m.z); mx.w = fmaxf(mx.w, m.w);
        mn.x = fminf(mn.x, m.x); mn.y = fminf(mn.y, m.y); mn.z = fminf(mn.z, m.z); mn.w = fminf(mn.w, m.w);
    }
    float invd = 1.0f / (float)(p1 - p0 + 1);
    float4 mean = make_float4(sum.x * invd, sum.y * invd, sum.z * invd, sum.w * invd);
    float4 sq = make_float4(ssq.x * invd, ssq.y * invd, ssq.z * invd, ssq.w * invd);
    float4 sd;
    sd.x = sqrtf(fmaxf(sq.x - mean.x * mean.x, 1e-6f));
    sd.y = sqrtf(fmaxf(sq.y - mean.y * mean.y, 1e-6f));
    sd.z = sqrtf(fmaxf(sq.z - mean.z * mean.z, 1e-6f));
    sd.w = sqrtf(fmaxf(sq.w - mean.w * mean.w, 1e-6f));
    __half* out = g_feats + (size_t)n * 512;
    *(uint2*)(out + 0 * 128 + lane * 4) = pack4h(mean);
    *(uint2*)(out + 1 * 128 + lane * 4) = pack4h(mx);
    *(uint2*)(out + 2 * 128 + lane * 4) = pack4h(mn);
    *(uint2*)(out + 3 * 128 + lane * 4) = pack4h(sd);
}

// ---------------- linear v6: single-term fp16, fp16 feats in, 2 CTAs/SM ----------------
#define SM_HDR 4096
#define BUFSZ 36864
#define OF_A  0
#define OF_BH 18432
#define ROWB 144
#define LIN_SMEM (SM_HDR + 2 * BUFSZ)   // 77824

__global__ void __launch_bounds__(256, 2) k_linear_mma(
    const __half* __restrict__ feats, const float* __restrict__ xin,
    const __half* __restrict__ Bh,
    const float* __restrict__ bias, const float* __restrict__ gam,
    const float* __restrict__ bet, float* __restrict__ xout) {
    extern __shared__ char smem[];
    uint32_t sb = smem_u32(smem);
    float* shf = (float*)smem;
    int t = threadIdx.x, wid = t >> 5, lane = t & 31;
    int m0 = blockIdx.x * 128;
    int wm = wid >> 1, wn = wid & 1;

    if (t < 128) {
        int node = min(m0 + t, NN - 1);
        float s1 = g_scale[node];
        shf[t] = s1;
        shf[128 + t] = 1.0f / fmaxf(s1, 1e-2f);
        shf[256 + t] = bias[t];
        shf[384 + t] = gam[t];
        shf[512 + t] = bet[t];
    }
    __syncthreads();

    float acc[2][8][4];
#pragma unroll
    for (int i = 0; i < 2; i++)
#pragma unroll
        for (int j = 0; j < 8; j++)
#pragma unroll
            for (int q = 0; q < 4; q++) acc[i][j][q] = 0.0f;

    // ldmatrix lane addressing
    int aidx = lane & 7, agrp = lane >> 3;
    int a_row = aidx + ((agrp & 1) ? 8 : 0);
    int a_kof = (agrp & 2) ? 8 : 0;
    int b_row = aidx + ((agrp & 2) ? 8 : 0);
    int b_kof = (agrp & 1) ? 8 : 0;

    float4 v[8];

#define BUFBASE(kt) (SM_HDR + ((kt) & 1) * BUFSZ)

#define ISSUE_B(kt) do { \
        const char* _bh = (const char*)(Bh + (size_t)(kt) * 8192); \
        uint32_t _bb = sb + BUFBASE(kt); \
        _Pragma("unroll") \
        for (int _q = 0; _q < 4; ++_q) { \
            int _i = t + _q * 256; \
            int _n = _i >> 3, _c = _i & 7; \
            cp16(_bb + OF_BH + _n * ROWB + _c * 16, _bh + _i * 16); \
        } \
    } while (0)

#define LOAD_A(kt) do { \
        int _c0 = (kt) * 64; \
        bool _isx = (_c0 >= 1536); \
        int _f = (_c0 >> 7) & 3, _ko = _c0 & 127; \
        _Pragma("unroll") \
        for (int _it = 0; _it < 8; ++_it) { \
            int _e = t + _it * 256; \
            int _m = _e >> 4, _kk = (_e & 15) * 4; \
            int _node = min(m0 + _m, NN - 1); \
            if (_isx) { \
                v[_it] = *(const float4*)(xin + (size_t)_node * 128 + (_c0 - 1536) + _kk); \
            } else { \
                uint2 _r = *(const uint2*)(feats + (size_t)_node * 512 + _f * 128 + _ko + _kk); \
                float2 _fa = __half22float2(*(__half2*)&_r.x); \
                float2 _fb = __half22float2(*(__half2*)&_r.y); \
                v[_it] = make_float4(_fa.x, _fa.y, _fb.x, _fb.y); \
            } \
        } \
    } while (0)

#define STORE_A(kt) do { \
        int _c0 = (kt) * 64; \
        int _j = _c0 >> 9; \
        bool _isx = (_c0 >= 1536); \
        char* _ab = smem + BUFBASE(kt); \
        _Pragma("unroll") \
        for (int _it = 0; _it < 8; ++_it) { \
            int _e = t + _it * 256; \
            int _m = _e >> 4, _kk = (_e & 15) * 4; \
            float _sm = (_isx || _j == 0) ? 1.0f : ((_j == 1) ? shf[_m] : shf[128 + _m]); \
            float4 _w = v[_it]; \
            __half2 _h0 = __floats2half2_rn(_w.x * _sm, _w.y * _sm); \
            __half2 _h1 = __floats2half2_rn(_w.z * _sm, _w.w * _sm); \
            uint2 _u; \
            _u.x = *(uint32_t*)&_h0; \
            _u.y = *(uint32_t*)&_h1; \
            *(uint2*)(_ab + OF_A + _m * ROWB + _kk * 2) = _u; \
        } \
    } while (0)

    LOAD_A(0);
    ISSUE_B(0);
    CP_COMMIT();
    STORE_A(0);
    CP_WAIT0();
    __syncthreads();

    for (int kt = 0; kt < NCHUNK; ++kt) {
        if (kt + 1 < NCHUNK) {
            LOAD_A(kt + 1);
            ISSUE_B(kt + 1);
        }
        CP_COMMIT();
        uint32_t tb = sb + BUFBASE(kt);
#pragma unroll
        for (int ks = 0; ks < 4; ++ks) {
            int kb = ks * 16;
            uint32_t ah[8], bfr[4];
            uint32_t a_off = (uint32_t)((wm * 32 + a_row) * ROWB + (kb + a_kof) * 2);
            ldm_x4(tb + OF_A + a_off, ah);
            ldm_x4(tb + OF_A + a_off + 16 * ROWB, ah + 4);
#pragma unroll
            for (int nt = 0; nt < 4; ++nt) {
                uint32_t b_off = (uint32_t)((wn * 64 + nt * 16 + b_row) * ROWB + (kb + b_kof) * 2);
                ldm_x4(tb + OF_BH + b_off, bfr);
                mma16816(acc[0][2 * nt], ah, bfr[0], bfr[1]);
                mma16816(acc[0][2 * nt + 1], ah, bfr[2], bfr[3]);
                mma16816(acc[1][2 * nt], ah + 4, bfr[0], bfr[1]);
                mma16816(acc[1][2 * nt + 1], ah + 4, bfr[2], bfr[3]);
            }
        }
        if (kt + 1 < NCHUNK) STORE_A(kt + 1);
        CP_WAIT0();
        __syncthreads();
    }

    // ---- epilogue: stage C, LN per row ----
    float* Cs = (float*)(smem + SM_HDR);  // [128][132] = 67584 B
    int g = lane >> 2, l2 = (lane & 3) * 2;
#pragma unroll
    for (int mi = 0; mi < 2; ++mi)
#pragma unroll
        for (int ni = 0; ni < 8; ++ni) {
            int row = wm * 32 + mi * 16 + g;
            int col = wn * 64 + ni * 8 + l2;
            *(float2*)(Cs + row * 132 + col) = make_float2(acc[mi][ni][0], acc[mi][ni][1]);
            *(float2*)(Cs + (row + 8) * 132 + col) = make_float2(acc[mi][ni][2], acc[mi][ni][3]);
        }
    __syncthreads();

    float4 b4 = *(const float4*)(shf + 256 + lane * 4);
    float4 g4 = *(const float4*)(shf + 384 + lane * 4);
    float4 be4 = *(const float4*)(shf + 512 + lane * 4);
    for (int r = wid; r < 128; r += 8) {
        int node = m0 + r;
        if (node >= NN) break;
        float4 vv = *(const float4*)(Cs + r * 132 + lane * 4);
        vv.x += b4.x; vv.y += b4.y; vv.z += b4.z; vv.w += b4.w;
        float s = vv.x + vv.y + vv.z + vv.w;
        float q = vv.x * vv.x + vv.y * vv.y + vv.z * vv.z + vv.w * vv.w;
#pragma unroll
        for (int off = 16; off > 0; off >>= 1) {
            s += __shfl_xor_sync(0xffffffffu, s, off);
            q += __shfl_xor_sync(0xffffffffu, q, off);
        }
        float mu = s * (1.0f / 128.0f);
        float var = q * (1.0f / 128.0f) - mu * mu;
        float rs = rsqrtf(var + 1e-5f);
        float4 xr = *(const float4*)(xin + (size_t)node * 128 + lane * 4);
        float4 o;
        o.x = fmaxf((vv.x - mu) * rs * g4.x + be4.x, 0.0f) + xr.x;
        o.y = fmaxf((vv.y - mu) * rs * g4.y + be4.y, 0.0f) + xr.y;
        o.z = fmaxf((vv.z - mu) * rs * g4.z + be4.z, 0.0f) + xr.z;
        o.w = fmaxf((vv.w - mu) * rs * g4.w + be4.w, 0.0f) + xr.w;
        *(float4*)(xout + (size_t)node * 128 + lane * 4) = o;
    }
}

// ---------------- DistMult scoring + state cleanup ----------------
__global__ void k_score(const float* __restrict__ x, const float* __restrict__ qw,
                        const int* __restrict__ src, const int* __restrict__ rel,
                        const int* __restrict__ dst, float* __restrict__ out) {
    int tid = blockIdx.x * blockDim.x + threadIdx.x;
    if (tid < NN) { g_deg[tid] = 0; g_pos[tid] = 0; }
    int i = tid >> 5;
    int lane = threadIdx.x & 31;
    if (i >= 32768) return;
    int s = src[i], r = rel[i], d = dst[i];
    float4 a = ((const float4*)(x + (size_t)s * DD))[lane];
    float4 q = ((const float4*)(qw + (size_t)r * DD))[lane];
    float4 b = ((const float4*)(x + (size_t)d * DD))[lane];
    float p = a.x * q.x * b.x + a.y * q.y * b.y + a.z * q.z * b.z + a.w * q.w * b.w;
#pragma unroll
    for (int off = 16; off > 0; off >>= 1) p += __shfl_xor_sync(0xffffffffu, p, off);
    if (lane == 0) out[i] = p;
}

// ---------------- launch ----------------
extern "C" void kernel_launch(void* const* d_in, const int* in_sizes, int n_in,
                              void* d_out, int out_size) {
    const float* x0   = (const float*)d_in[0];
    const int*   ei   = (const int*)d_in[1];
    const int*   etyp = (const int*)d_in[2];
    const float* ew   = (const float*)d_in[3];
    const float* relw = (const float*)d_in[4];
    const float* linw = (const float*)d_in[5];
    const float* linb = (const float*)d_in[6];
    const float* lng  = (const float*)d_in[7];
    const float* lnb  = (const float*)d_in[8];
    const float* qw   = (const float*)d_in[9];
    const int*   src  = (const int*)d_in[10];
    const int*   rel  = (const int*)d_in[11];
    const int*   dst  = (const int*)d_in[12];
    float* out = (float*)d_out;
    const int* es = ei;
    const int* ed = ei + NE;

    cudaFuncSetAttribute(k_linear_mma, cudaFuncAttributeMaxDynamicSharedMemorySize, LIN_SMEM);

    void *pa, *pb, *pf, *pbh;
    cudaGetSymbolAddress(&pa, g_xa);
    cudaGetSymbolAddress(&pb, g_xb);
    cudaGetSymbolAddress(&pf, g_feats);
    cudaGetSymbolAddress(&pbh, g_Bhi);
    float* XA = (float*)pa;
    float* XB = (float*)pb;
    __half* F = (__half*)pf;
    __half* BH = (__half*)pbh;

    k_hist<<<1954, 256>>>(ed);
    k_scanA<<<NBLK, 256>>>();
    k_fillB<<<1954, 256>>>(es, ed, etyp, ew);
    k_aggregate<<<6250, 256>>>(x0, x0, relw);   // launch 3: profiled
    k_prepw<<<4 * NCHUNK, 256>>>(linw);

    const float* xi = x0;
    float* xo = XA;
    for (int l = 0; l < 4; l++) {
        if (l > 0) k_aggregate<<<6250, 256>>>(xi, x0, relw + (size_t)l * 51 * 128);
        k_linear_mma<<<(NN + 127) / 128, 256, LIN_SMEM>>>(
            F, xi, BH + (size_t)l * NCHUNK * 8192,
            linb + l * 128, lng + l * 128, lnb + l * 128, xo);
        xi = xo;
        xo = (xo == XA) ? XB : XA;
    }
    k_score<<<4096, 256>>>(xi, qw, src, rel, dst, out);
}

// round 12
// speedup vs baseline: 1.0683x; 1.0683x over previous
#include <cuda_runtime.h>
#include <cuda_fp16.h>
#include <math.h>
#include <stdint.h>

#define NN 50000
#define NE 500000
#define DD 128
#define NCHUNK 26
#define NBLK 196   // ceil(50000/256)

// ---------------- device scratch ----------------
__device__ int    g_deg[NN];
__device__ int    g_pos[NN];
__device__ int    g_ptr[NN];        // scanA: block-local inclusive
__device__ int    g_ptr2[NN + 1];   // global exclusive (final CSR)
__device__ int    g_bsum[NBLK];
__device__ float  g_partial[NBLK];
__device__ int    g_ssrc[NE];
__device__ int    g_srel[NE];
__device__ float  g_sw[NE];
__device__ float  g_scale[NN];
__device__ __half g_feats[(size_t)NN * 512];
__device__ float  g_xa[(size_t)NN * DD];
__device__ float  g_xb[(size_t)NN * DD];
// transposed fp16 weight tiles: [4 layers][26 chunks][128 n][64 k]
__device__ __half g_Bhi[4 * NCHUNK * 8192];

__device__ __forceinline__ uint32_t smem_u32(const void* p) {
    uint32_t a;
    asm("{ .reg .u64 t; cvta.to.shared.u64 t, %1; cvt.u32.u64 %0, t; }" : "=r"(a) : "l"(p));
    return a;
}
__device__ __forceinline__ void ldm_x4(uint32_t addr, uint32_t* r) {
    asm volatile("ldmatrix.sync.aligned.m8n8.x4.shared.b16 {%0,%1,%2,%3}, [%4];"
                 : "=r"(r[0]), "=r"(r[1]), "=r"(r[2]), "=r"(r[3]) : "r"(addr));
}
__device__ __forceinline__ void mma16816(float* c, const uint32_t* a, uint32_t b0, uint32_t b1) {
    asm volatile(
        "mma.sync.aligned.m16n8k16.row.col.f32.f16.f16.f32 "
        "{%0,%1,%2,%3}, {%4,%5,%6,%7}, {%8,%9}, {%0,%1,%2,%3};"
        : "+f"(c[0]), "+f"(c[1]), "+f"(c[2]), "+f"(c[3])
        : "r"(a[0]), "r"(a[1]), "r"(a[2]), "r"(a[3]), "r"(b0), "r"(b1));
}
__device__ __forceinline__ void cp16(uint32_t dst, const void* src) {
    asm volatile("cp.async.cg.shared.global [%0], [%1], 16;" :: "r"(dst), "l"(src));
}
#define CP_COMMIT() asm volatile("cp.async.commit_group;" ::: "memory")
#define CP_WAIT0()  asm volatile("cp.async.wait_group 0;" ::: "memory")

__device__ __forceinline__ uint2 pack4h(float4 f) {
    __half2 a = __floats2half2_rn(f.x, f.y);
    __half2 b = __floats2half2_rn(f.z, f.w);
    uint2 u;
    u.x = *(uint32_t*)&a;
    u.y = *(uint32_t*)&b;
    return u;
}

// ---------------- CSR build ----------------
__global__ void k_hist(const int* __restrict__ ed) {
    int e = blockIdx.x * blockDim.x + threadIdx.x;
    if (e < NE) atomicAdd(&g_deg[ed[e]], 1);
}
// per-block inclusive scan + per-block log-degree partial sums
__global__ void k_scanA() {
    int b = blockIdx.x, t = threadIdx.x, i = b * 256 + t;
    int v = (i < NN) ? g_deg[i] : 0;
    int lane = t & 31, w = t >> 5;
    int x = v;
#pragma unroll
    for (int off = 1; off < 32; off <<= 1) {
        int y = __shfl_up_sync(0xffffffffu, x, off);
        if (lane >= off) x += y;
    }
    __shared__ int ws[8];
    __shared__ float ls[8];
    if (lane == 31) ws[w] = x;
    float lg = (i < NN) ? logf((float)v + 1.0f) : 0.0f;
#pragma unroll
    for (int off = 16; off > 0; off >>= 1) lg += __shfl_xor_sync(0xffffffffu, lg, off);
    if (lane == 0) ls[w] = lg;
    __syncthreads();
    int add = 0;
#pragma unroll
    for (int j = 0; j < 8; j++) if (j < w) add += ws[j];
    x += add;
    if (i < NN) g_ptr[i] = x;
    if (t == 255) g_bsum[b] = x;
    if (t == 0) {
        float s = 0;
#pragma unroll
        for (int j = 0; j < 8; j++) s += ls[j];
        g_partial[b] = s;
    }
}
// fused: scan block sums + finalize ptr + scatter edges + scale write
__global__ void k_fillB(const int* __restrict__ es, const int* __restrict__ ed,
                        const int* __restrict__ et, const float* __restrict__ ew) {
    __shared__ int sc[256];
    __shared__ int sOff[NBLK + 1];
    __shared__ float fs[256];
    int t = threadIdx.x, b = blockIdx.x;
    int v = (t < NBLK) ? g_bsum[t] : 0;
    sc[t] = v;
    fs[t] = (t < NBLK) ? g_partial[t] : 0.0f;
    __syncthreads();
#pragma unroll
    for (int off = 1; off < 256; off <<= 1) {
        int u = (t >= off) ? sc[t - off] : 0;
        __syncthreads();
        sc[t] += u;
        __syncthreads();
    }
    if (t < NBLK) sOff[t] = sc[t] - v;
    if (t == NBLK - 1) sOff[NBLK] = sc[t];
    __syncthreads();
#pragma unroll
    for (int off = 128; off > 0; off >>= 1) {
        if (t < off) fs[t] += fs[t + off];
        __syncthreads();
    }
    float factor = (float)NN / fs[0];
    int i = b * 256 + t;
    if (i < NN) {
        g_ptr2[i] = g_ptr[i] - g_deg[i] + sOff[i >> 8];
        g_scale[i] = logf((float)g_deg[i] + 1.0f) * factor;
    }
    if (i == 0) g_ptr2[NN] = sOff[NBLK];
    int e = b * 256 + t;
    if (e < NE) {
        int d = ed[e];
        int base = g_ptr[d] - g_deg[d] + sOff[d >> 8];
        int p = atomicAdd(&g_pos[d], 1);
        int slot = base + p;
        g_ssrc[slot] = es[e];
        g_srel[slot] = et[e];
        g_sw[slot] = ew[e];
    }
}

// ---------------- weight prep: smem transpose + fp16 ----------------
__global__ void k_prepw(const float* __restrict__ linw) {
    __shared__ float ts[64][129];
    int tile = blockIdx.x;
    int l = tile / NCHUNK, kt = tile - l * NCHUNK;
    const float* src = linw + ((size_t)l * 1664 + kt * 64) * 128;
    for (int i = threadIdx.x; i < 8192; i += 256) {
        int k = i >> 7, n = i & 127;
        ts[k][n] = src[i];
    }
    __syncthreads();
    __half* bh = g_Bhi + (size_t)tile * 8192;
    for (int i = threadIdx.x; i < 8192; i += 256) {
        int n = i >> 6, kk = i & 63;
        bh[i] = __float2half_rn(ts[kk][n]);
    }
}

// ---------------- aggregation: warp/node, depth-1 prefetch, fp16 feats out ----------------
__global__ void k_aggregate(const float* __restrict__ x, const float* __restrict__ x0,
                            const float* __restrict__ relw) {
    int gw = (blockIdx.x * blockDim.x + threadIdx.x) >> 5;
    int lane = threadIdx.x & 31;
    if (gw >= NN) return;
    int n = gw;
    float4 b = ((const float4*)(x0 + (size_t)n * DD))[lane];
    float4 sum = b, mx = b, mn = b;
    float4 ssq = make_float4(b.x * b.x, b.y * b.y, b.z * b.z, b.w * b.w);
    int p0 = g_ptr2[n], p1 = g_ptr2[n + 1];
    float4 xv, rv;
    float w = 0.f;
    if (p0 < p1) {
        int s = g_ssrc[p0], r = g_srel[p0];
        w = g_sw[p0];
        xv = ((const float4*)(x + (size_t)s * DD))[lane];
        rv = ((const float4*)(relw + (size_t)r * DD))[lane];
    }
    for (int p = p0; p < p1; ++p) {
        float4 cx = xv, cr = rv;
        float cw = w;
        if (p + 1 < p1) {
            int s2 = g_ssrc[p + 1], r2 = g_srel[p + 1];
            w = g_sw[p + 1];
            xv = ((const float4*)(x + (size_t)s2 * DD))[lane];
            rv = ((const float4*)(relw + (size_t)r2 * DD))[lane];
        }
        float4 m = make_float4(cx.x * cr.x * cw, cx.y * cr.y * cw, cx.z * cr.z * cw, cx.w * cr.w * cw);
        sum.x += m.x; sum.y += m.y; sum.z += m.z; sum.w += m.w;
        ssq.x += m.x * m.x; ssq.y += m.y * m.y; ssq.z += m.z * m.z; ssq.w += m.w * m.w;
        mx.x = fmaxf(mx.x, m.x); mx.y = fmaxf(mx.y, m.y); mx.z = fmaxf(mx.z, m.z); mx.w = fmaxf(mx.w, m.w);
        mn.x = fminf(mn.x, m.x); mn.y = fminf(mn.y, m.y); mn.z = fminf(mn.z, m.z); mn.w = fminf(mn.w, m.w);
    }
    float invd = 1.0f / (float)(p1 - p0 + 1);
    float4 mean = make_float4(sum.x * invd, sum.y * invd, sum.z * invd, sum.w * invd);
    float4 sq = make_float4(ssq.x * invd, ssq.y * invd, ssq.z * invd, ssq.w * invd);
    float4 sd;
    sd.x = sqrtf(fmaxf(sq.x - mean.x * mean.x, 1e-6f));
    sd.y = sqrtf(fmaxf(sq.y - mean.y * mean.y, 1e-6f));
    sd.z = sqrtf(fmaxf(sq.z - mean.z * mean.z, 1e-6f));
    sd.w = sqrtf(fmaxf(sq.w - mean.w * mean.w, 1e-6f));
    __half* out = g_feats + (size_t)n * 512;
    *(uint2*)(out + 0 * 128 + lane * 4) = pack4h(mean);
    *(uint2*)(out + 1 * 128 + lane * 4) = pack4h(mx);
    *(uint2*)(out + 2 * 128 + lane * 4) = pack4h(mn);
    *(uint2*)(out + 3 * 128 + lane * 4) = pack4h(sd);
}

// ---------------- linear v7: all-half A path ----------------
// kt 0-7  (j=0): A = raw fp16 feats -> direct cp.async gmem->smem
// kt 8-23 (j=1,2): A = feats * scale, HMUL2 in half domain
// kt 24-25: A = fp32 x -> convert
// CTA 128x128, 256 thr, 8 warps 4(M)x2(N), double-buffered, 2 CTAs/SM.
#define SM_HDR 4096
#define BUFSZ 36864
#define OF_A  0
#define OF_BH 18432
#define ROWB 144
#define LIN_SMEM (SM_HDR + 2 * BUFSZ)   // 77824

__global__ void __launch_bounds__(256, 2) k_linear_mma(
    const __half* __restrict__ feats, const float* __restrict__ xin,
    const __half* __restrict__ Bh,
    const float* __restrict__ bias, const float* __restrict__ gam,
    const float* __restrict__ bet, float* __restrict__ xout) {
    extern __shared__ char smem[];
    uint32_t sb = smem_u32(smem);
    float* shf = (float*)smem;
    uint32_t* shu = (uint32_t*)smem;
    int t = threadIdx.x, wid = t >> 5, lane = t & 31;
    int m0 = blockIdx.x * 128;
    int wm = wid >> 1, wn = wid & 1;

    if (t < 128) {
        int node = min(m0 + t, NN - 1);
        float s1 = g_scale[node];
        float s2 = 1.0f / fmaxf(s1, 1e-2f);
        __half2 h1 = __float2half2_rn(s1);
        __half2 h2 = __float2half2_rn(s2);
        shu[t] = *(uint32_t*)&h1;
        shu[128 + t] = *(uint32_t*)&h2;
        shf[256 + t] = bias[t];
        shf[384 + t] = gam[t];
        shf[512 + t] = bet[t];
    }
    __syncthreads();

    float acc[2][8][4];
#pragma unroll
    for (int i = 0; i < 2; i++)
#pragma unroll
        for (int j = 0; j < 8; j++)
#pragma unroll
            for (int q = 0; q < 4; q++) acc[i][j][q] = 0.0f;

    // ldmatrix lane addressing
    int aidx = lane & 7, agrp = lane >> 3;
    int a_row = aidx + ((agrp & 1) ? 8 : 0);
    int a_kof = (agrp & 2) ? 8 : 0;
    int b_row = aidx + ((agrp & 2) ? 8 : 0);
    int b_kof = (agrp & 1) ? 8 : 0;

    uint2 u[8];      // half-domain staging (feats scaled chunks)
    float4 vx[8];    // fp32 staging (x chunks)

#define BUFBASE(kt) (SM_HDR + ((kt) & 1) * BUFSZ)

#define ISSUE_B(kt) do { \
        const char* _bh = (const char*)(Bh + (size_t)(kt) * 8192); \
        uint32_t _bb = sb + BUFBASE(kt); \
        _Pragma("unroll") \
        for (int _q = 0; _q < 4; ++_q) { \
            int _i = t + _q * 256; \
            int _n = _i >> 3, _c = _i & 7; \
            cp16(_bb + OF_BH + _n * ROWB + _c * 16, _bh + _i * 16); \
        } \
    } while (0)

// j=0: direct gmem->smem copy of raw fp16 feats
#define ISSUE_A(kt) do { \
        int _c0 = (kt) * 64; \
        int _f = (_c0 >> 7) & 3, _ko = _c0 & 127; \
        uint32_t _bb = sb + BUFBASE(kt); \
        _Pragma("unroll") \
        for (int _q = 0; _q < 4; ++_q) { \
            int _i = t + _q * 256; \
            int _row = _i >> 3, _c = _i & 7; \
            int _node = min(m0 + _row, NN - 1); \
            cp16(_bb + OF_A + _row * ROWB + _c * 16, \
                 feats + (size_t)_node * 512 + _f * 128 + _ko + _c * 8); \
        } \
    } while (0)

#define LOAD_A(kt) do { \
        int _c0 = (kt) * 64; \
        bool _isx = (_c0 >= 1536); \
        int _f = (_c0 >> 7) & 3, _ko = _c0 & 127; \
        _Pragma("unroll") \
        for (int _it = 0; _it < 8; ++_it) { \
            int _e = t + _it * 256; \
            int _m = _e >> 4, _kk = (_e & 15) * 4; \
            int _node = min(m0 + _m, NN - 1); \
            if (_isx) { \
                vx[_it] = *(const float4*)(xin + (size_t)_node * 128 + (_c0 - 1536) + _kk); \
            } else { \
                u[_it] = *(const uint2*)(feats + (size_t)_node * 512 + _f * 128 + _ko + _kk); \
            } \
        } \
    } while (0)

#define STORE_A(kt) do { \
        int _c0 = (kt) * 64; \
        int _j = _c0 >> 9; \
        bool _isx = (_c0 >= 1536); \
        char* _ab = smem + BUFBASE(kt); \
        int _selb = (_j == 1) ? 0 : 128; \
        _Pragma("unroll") \
        for (int _it = 0; _it < 8; ++_it) { \
            int _e = t + _it * 256; \
            int _m = _e >> 4, _kk = (_e & 15) * 4; \
            uint2 _o; \
            if (_isx) { \
                float4 _w = vx[_it]; \
                __half2 _h0 = __floats2half2_rn(_w.x, _w.y); \
                __half2 _h1 = __floats2half2_rn(_w.z, _w.w); \
                _o.x = *(uint32_t*)&_h0; \
                _o.y = *(uint32_t*)&_h1; \
            } else { \
                uint32_t _scu = shu[_selb + _m]; \
                __half2 _sc = *(__half2*)&_scu; \
                __half2 _a = __hmul2(*(__half2*)&u[_it].x, _sc); \
                __half2 _b = __hmul2(*(__half2*)&u[_it].y, _sc); \
                _o.x = *(uint32_t*)&_a; \
                _o.y = *(uint32_t*)&_b; \
            } \
            *(uint2*)(_ab + OF_A + _m * ROWB + _kk * 2) = _o; \
        } \
    } while (0)

    // prologue: chunk 0 (j=0, direct A copy)
    ISSUE_A(0);
    ISSUE_B(0);
    CP_COMMIT();
    CP_WAIT0();
    __syncthreads();

    for (int kt = 0; kt < NCHUNK; ++kt) {
        int nx = kt + 1;
        bool haveNext = (nx < NCHUNK);
        bool nextDirect = haveNext && (nx < 8);
        if (haveNext) {
            if (nextDirect) ISSUE_A(nx);
            else LOAD_A(nx);
            ISSUE_B(nx);
        }
        CP_COMMIT();
        uint32_t tb = sb + BUFBASE(kt);
#pragma unroll
        for (int ks = 0; ks < 4; ++ks) {
            int kb = ks * 16;
            uint32_t ah[8], bfr[4];
            uint32_t a_off = (uint32_t)((wm * 32 + a_row) * ROWB + (kb + a_kof) * 2);
            ldm_x4(tb + OF_A + a_off, ah);
            ldm_x4(tb + OF_A + a_off + 16 * ROWB, ah + 4);
#pragma unroll
            for (int nt = 0; nt < 4; ++nt) {
                uint32_t b_off = (uint32_t)((wn * 64 + nt * 16 + b_row) * ROWB + (kb + b_kof) * 2);
                ldm_x4(tb + OF_BH + b_off, bfr);
                mma16816(acc[0][2 * nt], ah, bfr[0], bfr[1]);
                mma16816(acc[0][2 * nt + 1], ah, bfr[2], bfr[3]);
                mma16816(acc[1][2 * nt], ah + 4, bfr[0], bfr[1]);
                mma16816(acc[1][2 * nt + 1], ah + 4, bfr[2], bfr[3]);
            }
        }
        if (haveNext && !nextDirect) STORE_A(nx);
        CP_WAIT0();
        __syncthreads();
    }

    // ---- epilogue: stage C, LN per row ----
    float* Cs = (float*)(smem + SM_HDR);  // [128][132] = 67584 B
    int g = lane >> 2, l2 = (lane & 3) * 2;
#pragma unroll
    for (int mi = 0; mi < 2; ++mi)
#pragma unroll
        for (int ni = 0; ni < 8; ++ni) {
            int row = wm * 32 + mi * 16 + g;
            int col = wn * 64 + ni * 8 + l2;
            *(float2*)(Cs + row * 132 + col) = make_float2(acc[mi][ni][0], acc[mi][ni][1]);
            *(float2*)(Cs + (row + 8) * 132 + col) = make_float2(acc[mi][ni][2], acc[mi][ni][3]);
        }
    __syncthreads();

    float4 b4 = *(const float4*)(shf + 256 + lane * 4);
    float4 g4 = *(const float4*)(shf + 384 + lane * 4);
    float4 be4 = *(const float4*)(shf + 512 + lane * 4);
    for (int r = wid; r < 128; r += 8) {
        int node = m0 + r;
        if (node >= NN) break;
        float4 vv = *(const float4*)(Cs + r * 132 + lane * 4);
        vv.x += b4.x; vv.y += b4.y; vv.z += b4.z; vv.w += b4.w;
        float s = vv.x + vv.y + vv.z + vv.w;
        float q = vv.x * vv.x + vv.y * vv.y + vv.z * vv.z + vv.w * vv.w;
#pragma unroll
        for (int off = 16; off > 0; off >>= 1) {
            s += __shfl_xor_sync(0xffffffffu, s, off);
            q += __shfl_xor_sync(0xffffffffu, q, off);
        }
        float mu = s * (1.0f / 128.0f);
        float var = q * (1.0f / 128.0f) - mu * mu;
        float rs = rsqrtf(var + 1e-5f);
        float4 xr = *(const float4*)(xin + (size_t)node * 128 + lane * 4);
        float4 o;
        o.x = fmaxf((vv.x - mu) * rs * g4.x + be4.x, 0.0f) + xr.x;
        o.y = fmaxf((vv.y - mu) * rs * g4.y + be4.y, 0.0f) + xr.y;
        o.z = fmaxf((vv.z - mu) * rs * g4.z + be4.z, 0.0f) + xr.z;
        o.w = fmaxf((vv.w - mu) * rs * g4.w + be4.w, 0.0f) + xr.w;
        *(float4*)(xout + (size_t)node * 128 + lane * 4) = o;
    }
}

// ---------------- DistMult scoring + state cleanup ----------------
__global__ void k_score(const float* __restrict__ x, const float* __restrict__ qw,
                        const int* __restrict__ src, const int* __restrict__ rel,
                        const int* __restrict__ dst, float* __restrict__ out) {
    int tid = blockIdx.x * blockDim.x + threadIdx.x;
    if (tid < NN) { g_deg[tid] = 0; g_pos[tid] = 0; }
    int i = tid >> 5;
    int lane = threadIdx.x & 31;
    if (i >= 32768) return;
    int s = src[i], r = rel[i], d = dst[i];
    float4 a = ((const float4*)(x + (size_t)s * DD))[lane];
    float4 q = ((const float4*)(qw + (size_t)r * DD))[lane];
    float4 b = ((const float4*)(x + (size_t)d * DD))[lane];
    float p = a.x * q.x * b.x + a.y * q.y * b.y + a.z * q.z * b.z + a.w * q.w * b.w;
#pragma unroll
    for (int off = 16; off > 0; off >>= 1) p += __shfl_xor_sync(0xffffffffu, p, off);
    if (lane == 0) out[i] = p;
}

// ---------------- launch ----------------
extern "C" void kernel_launch(void* const* d_in, const int* in_sizes, int n_in,
                              void* d_out, int out_size) {
    const float* x0   = (const float*)d_in[0];
    const int*   ei   = (const int*)d_in[1];
    const int*   etyp = (const int*)d_in[2];
    const float* ew   = (const float*)d_in[3];
    const float* relw = (const float*)d_in[4];
    const float* linw = (const float*)d_in[5];
    const float* linb = (const float*)d_in[6];
    const float* lng  = (const float*)d_in[7];
    const float* lnb  = (const float*)d_in[8];
    const float* qw   = (const float*)d_in[9];
    const int*   src  = (const int*)d_in[10];
    const int*   rel  = (const int*)d_in[11];
    const int*   dst  = (const int*)d_in[12];
    float* out = (float*)d_out;
    const int* es = ei;
    const int* ed = ei + NE;

    cudaFuncSetAttribute(k_linear_mma, cudaFuncAttributeMaxDynamicSharedMemorySize, LIN_SMEM);

    void *pa, *pb, *pf, *pbh;
    cudaGetSymbolAddress(&pa, g_xa);
    cudaGetSymbolAddress(&pb, g_xb);
    cudaGetSymbolAddress(&pf, g_feats);
    cudaGetSymbolAddress(&pbh, g_Bhi);
    float* XA = (float*)pa;
    float* XB = (float*)pb;
    __half* F = (__half*)pf;
    __half* BH = (__half*)pbh;

    k_hist<<<1954, 256>>>(ed);
    k_scanA<<<NBLK, 256>>>();
    k_fillB<<<1954, 256>>>(es, ed, etyp, ew);
    k_aggregate<<<6250, 256>>>(x0, x0, relw);   // launch 3: profiled
    k_prepw<<<4 * NCHUNK, 256>>>(linw);

    const float* xi = x0;
    float* xo = XA;
    for (int l = 0; l < 4; l++) {
        if (l > 0) k_aggregate<<<6250, 256>>>(xi, x0, relw + (size_t)l * 51 * 128);
        k_linear_mma<<<(NN + 127) / 128, 256, LIN_SMEM>>>(
            F, xi, BH + (size_t)l * NCHUNK * 8192,
            linb + l * 128, lng + l * 128, lnb + l * 128, xo);
        xi = xo;
        xo = (xo == XA) ? XB : XA;
    }
    k_score<<<4096, 256>>>(xi, qw, src, rel, dst, out);
}